// round 6
// baseline (speedup 1.0000x reference)
#include <cuda_runtime.h>
#include <cuda_bf16.h>
#include <stdint.h>

#define TOKS 8192
#define DIMD 512
#define HIDH 1024
#define NEXP 16
#define PCAP 16384
#define MT   20                      // max M-tiles per expert (2560 cap, >30 sigma)
#define HROWS (PCAP + 128 * MT)      // hidden buffer rows (slack for last tile)

// ---------------- device scratch ----------------
__device__ int   g_cnt[NEXP];
__device__ int   g_off[NEXP + 1];
__device__ int   g_cur[NEXP];
__device__ int   g_tok[PCAP];
__device__ float g_wgt[PCAP];
__device__ __align__(256) __nv_bfloat16 g_xh[TOKS * DIMD];
__device__ __align__(256) __nv_bfloat16 g_xl[TOKS * DIMD];
__device__ __align__(256) __nv_bfloat16 g_w1h[NEXP * HIDH * DIMD];   // W1^T hi: [e][h][d]
__device__ __align__(256) __nv_bfloat16 g_w1l[NEXP * HIDH * DIMD];
__device__ __align__(256) __nv_bfloat16 g_w2h[NEXP * DIMD * HIDH];   // W2^T hi: [e][dout][h]
__device__ __align__(256) __nv_bfloat16 g_w2l[NEXP * DIMD * HIDH];
__device__ __align__(256) __nv_bfloat16 g_hh[(size_t)HROWS * HIDH];  // gelu hidden hi
__device__ __align__(256) __nv_bfloat16 g_hl[(size_t)HROWS * HIDH];  // gelu hidden lo

// ---------------- helpers ----------------
__device__ __forceinline__ uint32_t smem_u32(const void* p) {
    uint32_t a;
    asm("{ .reg .u64 t; cvta.to.shared.u64 t, %1; cvt.u32.u64 %0, t; }" : "=r"(a) : "l"(p));
    return a;
}
__device__ __forceinline__ uint32_t sw128(uint32_t o) { return o ^ ((o >> 3) & 0x70); }

__device__ __forceinline__ void cpa16(uint32_t dst, const void* src, uint32_t sz) {
    asm volatile("cp.async.cg.shared.global [%0], [%1], 16, %2;"
                 :: "r"(dst), "l"(src), "r"(sz) : "memory");
}
__device__ __forceinline__ void cp_commit() {
    asm volatile("cp.async.commit_group;" ::: "memory");
}
template <int N>
__device__ __forceinline__ void cp_wait() {
    asm volatile("cp.async.wait_group %0;" :: "n"(N) : "memory");
}
__device__ __forceinline__ void ldsm4(uint32_t* r, uint32_t addr) {
    asm volatile("ldmatrix.sync.aligned.m8n8.x4.shared.b16 {%0,%1,%2,%3}, [%4];"
                 : "=r"(r[0]), "=r"(r[1]), "=r"(r[2]), "=r"(r[3]) : "r"(addr));
}
__device__ __forceinline__ void mma_bf16(float* d, const uint32_t* a, const uint32_t* b) {
    asm volatile(
        "mma.sync.aligned.m16n8k16.row.col.f32.bf16.bf16.f32 "
        "{%0,%1,%2,%3}, {%4,%5,%6,%7}, {%8,%9}, {%0,%1,%2,%3};"
        : "+f"(d[0]), "+f"(d[1]), "+f"(d[2]), "+f"(d[3])
        : "r"(a[0]), "r"(a[1]), "r"(a[2]), "r"(a[3]), "r"(b[0]), "r"(b[1]));
}

// smem layout (dynamic): s_tok[128] @0, s_wgt[128] @512, stages @1024
#define OFF_AHI 0
#define OFF_ALO 16384
#define OFF_BHI 32768
#define OFF_BLO 49152
#define STG     65536
#define SM_STAGE 1024
#define SMEM_DYN (SM_STAGE + 2 * STG)

extern __shared__ __align__(1024) char smc[];

// ---------------- routing / prep kernels ----------------
__global__ void k_init_out(float* out, int n) {
    int stride = gridDim.x * blockDim.x;
    for (int i = blockIdx.x * blockDim.x + threadIdx.x; i < n; i += stride) out[i] = 0.0f;
    if (blockIdx.x == 0 && threadIdx.x < NEXP) g_cnt[threadIdx.x] = 0;
}
__global__ void k_count(const float* __restrict__ rt) {
    int i = blockIdx.x * 256 + threadIdx.x;
    if (i < TOKS * NEXP && rt[i] > 0.0f) atomicAdd(&g_cnt[i & (NEXP - 1)], 1);
}
__global__ void k_scan() {
    if (threadIdx.x == 0) {
        int acc = 0;
        for (int e = 0; e < NEXP; e++) { g_off[e] = acc; g_cur[e] = acc; acc += g_cnt[e]; }
        g_off[NEXP] = acc;
    }
}
__global__ void k_assign(const float* __restrict__ rt) {
    int i = blockIdx.x * 256 + threadIdx.x;
    if (i < TOKS * NEXP) {
        float s = rt[i];
        if (s > 0.0f) {
            int slot = atomicAdd(&g_cur[i & (NEXP - 1)], 1);
            if (slot < PCAP) { g_tok[slot] = i >> 4; g_wgt[slot] = s; }
        }
    }
}
__global__ void k_split_x(const float* __restrict__ x) {
    int i = blockIdx.x * 256 + threadIdx.x;
    if (i < TOKS * DIMD) {
        float v = x[i];
        __nv_bfloat16 h = __float2bfloat16(v);
        g_xh[i] = h;
        g_xl[i] = __float2bfloat16(v - __bfloat162float(h));
    }
}
// transpose + hi/lo split: W [e][R][C] (C contig) -> T [e][C][R]
__global__ void k_tsplit(const float* __restrict__ W, int which, int R, int C) {
    __shared__ float tile[32][33];
    int e = blockIdx.z, c0 = blockIdx.x * 32, r0 = blockIdx.y * 32;
    const float* We = W + (size_t)e * R * C;
    for (int i = threadIdx.y; i < 32; i += 8)
        tile[i][threadIdx.x] = We[(size_t)(r0 + i) * C + c0 + threadIdx.x];
    __syncthreads();
    __nv_bfloat16* Th = (which ? g_w2h : g_w1h) + (size_t)e * R * C;
    __nv_bfloat16* Tl = (which ? g_w2l : g_w1l) + (size_t)e * R * C;
    for (int i = threadIdx.y; i < 32; i += 8) {
        float v = tile[threadIdx.x][i];
        __nv_bfloat16 h = __float2bfloat16(v);
        size_t o = (size_t)(c0 + i) * R + r0 + threadIdx.x;
        Th[o] = h;
        Tl[o] = __float2bfloat16(v - __bfloat162float(h));
    }
}

// ---------------- shared GEMM tile compute ----------------
// CTA 128x128, BK=64, 8 warps: wm = wid&3 (32 rows), wn = wid>>2 (64 cols)
__device__ __forceinline__ void tile_compute(uint32_t stg, int wm, int wn, int lane,
                                             float acc[2][8][4]) {
    int arow = (lane & 15), acsel = (lane >> 4) << 4;
    int brow = ((lane >> 4) << 3) + (lane & 7), bcsel = ((lane >> 3) & 1) << 4;
    #pragma unroll
    for (int ks = 0; ks < 4; ++ks) {
        uint32_t ah[2][4], al[2][4], bh[4][4], bl[4][4];
        #pragma unroll
        for (int mi = 0; mi < 2; ++mi) {
            uint32_t off = sw128((uint32_t)((wm * 32 + mi * 16 + arow) << 7) + ks * 32 + acsel);
            ldsm4(ah[mi], stg + OFF_AHI + off);
            ldsm4(al[mi], stg + OFF_ALO + off);
        }
        #pragma unroll
        for (int np = 0; np < 4; ++np) {
            uint32_t off = sw128((uint32_t)((wn * 64 + np * 16 + brow) << 7) + ks * 32 + bcsel);
            ldsm4(bh[np], stg + OFF_BHI + off);
            ldsm4(bl[np], stg + OFF_BLO + off);
        }
        #pragma unroll
        for (int mi = 0; mi < 2; ++mi)
            #pragma unroll
            for (int np = 0; np < 4; ++np) {
                mma_bf16(acc[mi][np * 2],     ah[mi], &bh[np][0]);
                mma_bf16(acc[mi][np * 2],     ah[mi], &bl[np][0]);
                mma_bf16(acc[mi][np * 2],     al[mi], &bh[np][0]);
                mma_bf16(acc[mi][np * 2 + 1], ah[mi], &bh[np][2]);
                mma_bf16(acc[mi][np * 2 + 1], ah[mi], &bl[np][2]);
                mma_bf16(acc[mi][np * 2 + 1], al[mi], &bh[np][2]);
            }
    }
}

// ---------------- GEMM1: H = gelu(Xg @ W1 + b1), split bf16 ----------------
__global__ __launch_bounds__(256, 1) void k_gemm1(const float* __restrict__ b1) {
    int e = blockIdx.z, mt = blockIdx.y, nt = blockIdx.x;
    int base = g_off[e], cnt = g_off[e + 1] - base;
    if (mt * 128 >= cnt) return;
    int vrows = cnt - mt * 128;                 // valid rows in this tile
    if (vrows > 128) vrows = 128;

    uint32_t sb = smem_u32(smc);
    int tid = threadIdx.x, wid = tid >> 5, lane = tid & 31;
    int wm = wid & 3, wn = wid >> 2;
    int* s_tok = (int*)smc;
    if (tid < 128) {
        int gi = mt * 128 + tid;
        s_tok[tid] = (gi < cnt) ? g_tok[base + gi] : -1;
    }
    __syncthreads();

    float acc[2][8][4];
    #pragma unroll
    for (int i = 0; i < 2; ++i)
        #pragma unroll
        for (int j = 0; j < 8; ++j)
            #pragma unroll
            for (int q = 0; q < 4; ++q) acc[i][j][q] = 0.0f;

    auto issue = [&](int buf, int k0) {
        uint32_t stg = sb + SM_STAGE + buf * STG;
        #pragma unroll
        for (int it = 0; it < 4; ++it) {
            int ch = tid + it * 256;
            int row = ch >> 3, c16 = ch & 7;
            uint32_t sw = sw128((uint32_t)(row << 7) + (c16 << 4));
            int tok = s_tok[row];
            size_t ao = (size_t)(tok < 0 ? 0 : tok) * DIMD + k0 + c16 * 8;
            uint32_t sz = (tok < 0) ? 0u : 16u;
            cpa16(stg + OFF_AHI + sw, g_xh + ao, sz);
            cpa16(stg + OFF_ALO + sw, g_xl + ao, sz);
            size_t bo = ((size_t)e * HIDH + nt * 128 + row) * DIMD + k0 + c16 * 8;
            cpa16(stg + OFF_BHI + sw, g_w1h + bo, 16u);
            cpa16(stg + OFF_BLO + sw, g_w1l + bo, 16u);
        }
        cp_commit();
    };

    const int KC = DIMD / 64;  // 8
    issue(0, 0);
    for (int kc = 0; kc < KC; ++kc) {
        if (kc + 1 < KC) { issue((kc + 1) & 1, (kc + 1) * 64); cp_wait<1>(); }
        else             { cp_wait<0>(); }
        __syncthreads();
        tile_compute(sb + SM_STAGE + (kc & 1) * STG, wm, wn, lane, acc);
        __syncthreads();
    }

    // epilogue: +bias, exact GELU, split, store H — ONLY valid rows
    // (padding rows would alias the next expert's compact slots -> race)
    int r_lo = lane >> 2, cb = (lane & 3) * 2;
    size_t slot0 = (size_t)(base + mt * 128);
    const float* b1e = b1 + (size_t)e * HIDH;
    #pragma unroll
    for (int mi = 0; mi < 2; ++mi)
        #pragma unroll
        for (int hh = 0; hh < 2; ++hh) {
            int row = wm * 32 + mi * 16 + hh * 8 + r_lo;
            if (row >= vrows) continue;
            size_t sbase = (slot0 + row) * HIDH;
            #pragma unroll
            for (int ni = 0; ni < 8; ++ni) {
                int col = nt * 128 + wn * 64 + ni * 8 + cb;
                float v0 = acc[mi][ni][hh * 2 + 0] + b1e[col];
                float v1 = acc[mi][ni][hh * 2 + 1] + b1e[col + 1];
                float q0 = 0.5f * v0 * (1.0f + erff(v0 * 0.70710678118654752f));
                float q1 = 0.5f * v1 * (1.0f + erff(v1 * 0.70710678118654752f));
                __nv_bfloat16 h0 = __float2bfloat16(q0), h1 = __float2bfloat16(q1);
                __nv_bfloat16 l0 = __float2bfloat16(q0 - __bfloat162float(h0));
                __nv_bfloat16 l1 = __float2bfloat16(q1 - __bfloat162float(h1));
                *(__nv_bfloat162*)(g_hh + sbase + col) = __halves2bfloat162(h0, h1);
                *(__nv_bfloat162*)(g_hl + sbase + col) = __halves2bfloat162(l0, l1);
            }
        }
}

// ---------------- GEMM2: Y = H @ W2 + b2; out[tok] += w * Y ----------------
__global__ __launch_bounds__(256, 1) void k_gemm2(const float* __restrict__ b2,
                                                  float* __restrict__ out) {
    int e = blockIdx.z, mt = blockIdx.y, nt = blockIdx.x;
    int base = g_off[e], cnt = g_off[e + 1] - base;
    if (mt * 128 >= cnt) return;

    uint32_t sb = smem_u32(smc);
    int tid = threadIdx.x, wid = tid >> 5, lane = tid & 31;
    int wm = wid & 3, wn = wid >> 2;
    int* s_tok = (int*)smc;
    float* s_wgt = (float*)(smc + 512);
    if (tid < 128) {
        int gi = mt * 128 + tid;
        bool ok = gi < cnt;
        s_tok[tid] = ok ? g_tok[base + gi] : -1;
        s_wgt[tid] = ok ? g_wgt[base + gi] : 0.0f;
    }
    __syncthreads();

    float acc[2][8][4];
    #pragma unroll
    for (int i = 0; i < 2; ++i)
        #pragma unroll
        for (int j = 0; j < 8; ++j)
            #pragma unroll
            for (int q = 0; q < 4; ++q) acc[i][j][q] = 0.0f;

    auto issue = [&](int buf, int k0) {
        uint32_t stg = sb + SM_STAGE + buf * STG;
        #pragma unroll
        for (int it = 0; it < 4; ++it) {
            int ch = tid + it * 256;
            int row = ch >> 3, c16 = ch & 7;
            uint32_t sw = sw128((uint32_t)(row << 7) + (c16 << 4));
            // padding rows (>= cnt) read stale/zero hidden data; their results
            // are discarded in the epilogue (tok=-1), rows are independent.
            size_t ao = (size_t)(base + mt * 128 + row) * HIDH + k0 + c16 * 8;
            cpa16(stg + OFF_AHI + sw, g_hh + ao, 16u);
            cpa16(stg + OFF_ALO + sw, g_hl + ao, 16u);
            size_t bo = ((size_t)e * DIMD + nt * 128 + row) * HIDH + k0 + c16 * 8;
            cpa16(stg + OFF_BHI + sw, g_w2h + bo, 16u);
            cpa16(stg + OFF_BLO + sw, g_w2l + bo, 16u);
        }
        cp_commit();
    };

    const int KC = HIDH / 64;  // 16
    issue(0, 0);
    for (int kc = 0; kc < KC; ++kc) {
        if (kc + 1 < KC) { issue((kc + 1) & 1, (kc + 1) * 64); cp_wait<1>(); }
        else             { cp_wait<0>(); }
        __syncthreads();
        tile_compute(sb + SM_STAGE + (kc & 1) * STG, wm, wn, lane, acc);
        __syncthreads();
    }

    // epilogue: +b2, weighted scatter-add into out
    int r_lo = lane >> 2, cb = (lane & 3) * 2;
    const float* b2e = b2 + (size_t)e * DIMD;
    #pragma unroll
    for (int mi = 0; mi < 2; ++mi)
        #pragma unroll
        for (int hh = 0; hh < 2; ++hh) {
            int row = wm * 32 + mi * 16 + hh * 8 + r_lo;
            int tok = s_tok[row];
            float w = s_wgt[row];
            if (tok < 0 || w == 0.0f) continue;
            float* orow = out + (size_t)tok * DIMD;
            #pragma unroll
            for (int ni = 0; ni < 8; ++ni) {
                int col = nt * 128 + wn * 64 + ni * 8 + cb;
                float y0 = acc[mi][ni][hh * 2 + 0] + b2e[col];
                float y1 = acc[mi][ni][hh * 2 + 1] + b2e[col + 1];
                atomicAdd(orow + col,     w * y0);
                atomicAdd(orow + col + 1, w * y1);
            }
        }
}

// ---------------- launch ----------------
extern "C" void kernel_launch(void* const* d_in, const int* in_sizes, int n_in,
                              void* d_out, int out_size) {
    const float* x  = (const float*)d_in[0];
    const float* rt = (const float*)d_in[1];
    const float* W1 = (const float*)d_in[2];
    const float* b1 = (const float*)d_in[3];
    const float* W2 = (const float*)d_in[4];
    const float* b2 = (const float*)d_in[5];
    float* out = (float*)d_out;

    cudaFuncSetAttribute(k_gemm1, cudaFuncAttributeMaxDynamicSharedMemorySize, SMEM_DYN);
    cudaFuncSetAttribute(k_gemm2, cudaFuncAttributeMaxDynamicSharedMemorySize, SMEM_DYN);

    k_init_out<<<256, 256>>>(out, out_size);
    int nr = (TOKS * NEXP + 255) / 256;
    k_count<<<nr, 256>>>(rt);
    k_scan<<<1, 32>>>();
    k_assign<<<nr, 256>>>(rt);
    k_split_x<<<(TOKS * DIMD + 255) / 256, 256>>>(x);
    dim3 tb(32, 8);
    k_tsplit<<<dim3(HIDH / 32, DIMD / 32, NEXP), tb>>>(W1, 0, DIMD, HIDH);
    k_tsplit<<<dim3(DIMD / 32, HIDH / 32, NEXP), tb>>>(W2, 1, HIDH, DIMD);
    k_gemm1<<<dim3(HIDH / 128, MT, NEXP), 256, SMEM_DYN>>>(b1);
    k_gemm2<<<dim3(DIMD / 128, MT, NEXP), 256, SMEM_DYN>>>(b2, out);
}

// round 7
// speedup vs baseline: 1.0366x; 1.0366x over previous
#include <cuda_runtime.h>
#include <cuda_bf16.h>
#include <stdint.h>

#define TOKS 8192
#define DIMD 512
#define HIDH 1024
#define NEXP 16
#define ECAP 2048                    // fixed capacity per expert (mean 1024, 33 sigma)
#define HROWS (NEXP * ECAP)

// ---------------- device scratch ----------------
__device__ int   g_cnt[NEXP];
__device__ int   g_tok[NEXP * ECAP];
__device__ float g_wgt[NEXP * ECAP];
__device__ __align__(256) __nv_bfloat16 g_xh[TOKS * DIMD];
__device__ __align__(256) __nv_bfloat16 g_xl[TOKS * DIMD];
__device__ __align__(256) __nv_bfloat16 g_w1h[NEXP * HIDH * DIMD];   // W1^T hi: [e][h][d]
__device__ __align__(256) __nv_bfloat16 g_w1l[NEXP * HIDH * DIMD];
__device__ __align__(256) __nv_bfloat16 g_w2h[NEXP * DIMD * HIDH];   // W2^T hi: [e][dout][h]
__device__ __align__(256) __nv_bfloat16 g_w2l[NEXP * DIMD * HIDH];
__device__ __align__(256) __nv_bfloat16 g_hh[(size_t)HROWS * HIDH];  // gelu hidden hi
__device__ __align__(256) __nv_bfloat16 g_hl[(size_t)HROWS * HIDH];  // gelu hidden lo

// ---------------- helpers ----------------
__device__ __forceinline__ uint32_t smem_u32(const void* p) {
    uint32_t a;
    asm("{ .reg .u64 t; cvta.to.shared.u64 t, %1; cvt.u32.u64 %0, t; }" : "=r"(a) : "l"(p));
    return a;
}
__device__ __forceinline__ uint32_t sw128(uint32_t o) { return o ^ ((o >> 3) & 0x70); }

__device__ __forceinline__ void cpa16(uint32_t dst, const void* src, uint32_t sz) {
    asm volatile("cp.async.cg.shared.global [%0], [%1], 16, %2;"
                 :: "r"(dst), "l"(src), "r"(sz) : "memory");
}
__device__ __forceinline__ void cp_commit() {
    asm volatile("cp.async.commit_group;" ::: "memory");
}
template <int N>
__device__ __forceinline__ void cp_wait() {
    asm volatile("cp.async.wait_group %0;" :: "n"(N) : "memory");
}
__device__ __forceinline__ void ldsm4(uint32_t* r, uint32_t addr) {
    asm volatile("ldmatrix.sync.aligned.m8n8.x4.shared.b16 {%0,%1,%2,%3}, [%4];"
                 : "=r"(r[0]), "=r"(r[1]), "=r"(r[2]), "=r"(r[3]) : "r"(addr));
}
__device__ __forceinline__ void mma_bf16(float* d, const uint32_t* a, const uint32_t* b) {
    asm volatile(
        "mma.sync.aligned.m16n8k16.row.col.f32.bf16.bf16.f32 "
        "{%0,%1,%2,%3}, {%4,%5,%6,%7}, {%8,%9}, {%0,%1,%2,%3};"
        : "+f"(d[0]), "+f"(d[1]), "+f"(d[2]), "+f"(d[3])
        : "r"(a[0]), "r"(a[1]), "r"(a[2]), "r"(a[3]), "r"(b[0]), "r"(b[1]));
}

// smem: s_tok[128] @0, s_wgt[128] @512, 3 stages @1024
// stage: A[128 rows x 128B] + B[128 rows x 128B]; row = [hi K32 (64B) | lo K32 (64B)]
#define STG      32768
#define STG_B    16384
#define SM_STAGE 1024
#define SMEM_DYN (SM_STAGE + 3 * STG)   // 99328

extern __shared__ __align__(1024) char smc[];

// ---------------- prep kernels ----------------
__global__ void k_split_x(const float* __restrict__ x) {
    if (blockIdx.x == 0 && threadIdx.x < NEXP) g_cnt[threadIdx.x] = 0;
    int i = blockIdx.x * 256 + threadIdx.x;
    if (i < TOKS * DIMD / 4) {
        float4 v = ((const float4*)x)[i];
        __nv_bfloat16 h0 = __float2bfloat16(v.x), h1 = __float2bfloat16(v.y);
        __nv_bfloat16 h2 = __float2bfloat16(v.z), h3 = __float2bfloat16(v.w);
        __nv_bfloat16 l0 = __float2bfloat16(v.x - __bfloat162float(h0));
        __nv_bfloat16 l1 = __float2bfloat16(v.y - __bfloat162float(h1));
        __nv_bfloat16 l2 = __float2bfloat16(v.z - __bfloat162float(h2));
        __nv_bfloat16 l3 = __float2bfloat16(v.w - __bfloat162float(h3));
        ((__nv_bfloat162*)g_xh)[i * 2]     = __halves2bfloat162(h0, h1);
        ((__nv_bfloat162*)g_xh)[i * 2 + 1] = __halves2bfloat162(h2, h3);
        ((__nv_bfloat162*)g_xl)[i * 2]     = __halves2bfloat162(l0, l1);
        ((__nv_bfloat162*)g_xl)[i * 2 + 1] = __halves2bfloat162(l2, l3);
    }
}

// single-pass routing into fixed-capacity per-expert lists
__global__ void k_scatter(const float* __restrict__ rt) {
    __shared__ int s_cnt[NEXP], s_base[NEXP];
    int tid = threadIdx.x;
    int n = blockIdx.x * 256 + tid;
    if (tid < NEXP) s_cnt[tid] = 0;
    __syncthreads();
    float v[NEXP];
    const float4* r4 = (const float4*)(rt + (size_t)n * NEXP);
    float4 a = r4[0], b = r4[1], c = r4[2], d = r4[3];
    v[0]=a.x; v[1]=a.y; v[2]=a.z; v[3]=a.w; v[4]=b.x; v[5]=b.y; v[6]=b.z; v[7]=b.w;
    v[8]=c.x; v[9]=c.y; v[10]=c.z; v[11]=c.w; v[12]=d.x; v[13]=d.y; v[14]=d.z; v[15]=d.w;
    int le[4]; float lv[4]; int ls[4]; int k = 0;
    #pragma unroll
    for (int e = 0; e < NEXP; ++e)
        if (v[e] > 0.0f && k < 4) { le[k] = e; lv[k] = v[e]; ls[k] = atomicAdd(&s_cnt[e], 1); ++k; }
    __syncthreads();
    if (tid < NEXP) s_base[tid] = atomicAdd(&g_cnt[tid], s_cnt[tid]);
    __syncthreads();
    for (int j = 0; j < k; ++j) {
        int slot = s_base[le[j]] + ls[j];
        if (slot < ECAP) { g_tok[le[j] * ECAP + slot] = n; g_wgt[le[j] * ECAP + slot] = lv[j]; }
    }
}

// transpose + hi/lo split: W [e][R][C] (C contig) -> T [e][C][R]
__global__ void k_tsplit(const float* __restrict__ W, int which, int R, int C) {
    __shared__ float tile[32][33];
    int e = blockIdx.z, c0 = blockIdx.x * 32, r0 = blockIdx.y * 32;
    const float* We = W + (size_t)e * R * C;
    int tx = threadIdx.x, ty = threadIdx.y;
    for (int i = ty; i < 32; i += 8)
        tile[i][tx] = We[(size_t)(r0 + i) * C + c0 + tx];
    __syncthreads();
    __nv_bfloat16* Th = (which ? g_w2h : g_w1h) + (size_t)e * R * C;
    __nv_bfloat16* Tl = (which ? g_w2l : g_w1l) + (size_t)e * R * C;
    int tid = ty * 32 + tx;
    #pragma unroll
    for (int w = tid; w < 512; w += 256) {
        int c = w >> 4, rp = (w & 15) * 2;
        float v0 = tile[rp][c], v1 = tile[rp + 1][c];
        __nv_bfloat16 h0 = __float2bfloat16(v0), h1 = __float2bfloat16(v1);
        __nv_bfloat16 l0 = __float2bfloat16(v0 - __bfloat162float(h0));
        __nv_bfloat16 l1 = __float2bfloat16(v1 - __bfloat162float(h1));
        size_t o = (size_t)(c0 + c) * R + r0 + rp;
        *(__nv_bfloat162*)(Th + o) = __halves2bfloat162(h0, h1);
        *(__nv_bfloat162*)(Tl + o) = __halves2bfloat162(l0, l1);
    }
}

__global__ void k_init_out(float* out, int n4) {
    int stride = gridDim.x * blockDim.x;
    float4 z = make_float4(0.f, 0.f, 0.f, 0.f);
    for (int i = blockIdx.x * blockDim.x + threadIdx.x; i < n4; i += stride)
        ((float4*)out)[i] = z;
}

// ---------------- GEMM tile compute ----------------
// CTA 128x128, BK=32 per stage, 8 warps: wm = wid&3 (32 rows), wn = wid>>2 (64 cols)
__device__ __forceinline__ void tile_compute(uint32_t stg, int wm, int wn, int lane,
                                             float acc[2][8][4]) {
    int arow = lane & 15, acol = (lane >> 4) << 4;
    int brow = ((lane >> 4) << 3) + (lane & 7), bcol = ((lane >> 3) & 1) << 4;
    #pragma unroll
    for (int ks = 0; ks < 2; ++ks) {
        uint32_t ah[2][4], al[2][4], bh[4][4], bl[4][4];
        #pragma unroll
        for (int mi = 0; mi < 2; ++mi) {
            uint32_t rb = (uint32_t)((wm * 32 + mi * 16 + arow) << 7);
            ldsm4(ah[mi], stg + sw128(rb + ks * 32 + acol));
            ldsm4(al[mi], stg + sw128(rb + 64 + ks * 32 + acol));
        }
        #pragma unroll
        for (int np = 0; np < 4; ++np) {
            uint32_t rb = (uint32_t)((wn * 64 + np * 16 + brow) << 7);
            ldsm4(bh[np], stg + STG_B + sw128(rb + ks * 32 + bcol));
            ldsm4(bl[np], stg + STG_B + sw128(rb + 64 + ks * 32 + bcol));
        }
        #pragma unroll
        for (int mi = 0; mi < 2; ++mi)
            #pragma unroll
            for (int np = 0; np < 4; ++np) {
                mma_bf16(acc[mi][np * 2],     ah[mi], &bh[np][0]);
                mma_bf16(acc[mi][np * 2],     ah[mi], &bl[np][0]);
                mma_bf16(acc[mi][np * 2],     al[mi], &bh[np][0]);
                mma_bf16(acc[mi][np * 2 + 1], ah[mi], &bh[np][2]);
                mma_bf16(acc[mi][np * 2 + 1], ah[mi], &bl[np][2]);
                mma_bf16(acc[mi][np * 2 + 1], al[mi], &bh[np][2]);
            }
    }
}

// ---------------- GEMM1: H = gelu(Xg @ W1 + b1), split bf16 ----------------
__global__ __launch_bounds__(256, 2) void k_gemm1(const float* __restrict__ b1) {
    int e = blockIdx.z, mt = blockIdx.y, nt = blockIdx.x;
    int cnt = g_cnt[e];
    if (cnt > ECAP) cnt = ECAP;
    if (mt * 128 >= cnt) return;
    int vrows = cnt - mt * 128;
    if (vrows > 128) vrows = 128;

    uint32_t sb = smem_u32(smc);
    int tid = threadIdx.x, wid = tid >> 5, lane = tid & 31;
    int wm = wid & 3, wn = wid >> 2;
    int* s_tok = (int*)smc;
    if (tid < 128) {
        int gi = mt * 128 + tid;
        s_tok[tid] = (gi < cnt) ? g_tok[e * ECAP + gi] : -1;
    }
    __syncthreads();

    float acc[2][8][4];
    #pragma unroll
    for (int i = 0; i < 2; ++i)
        #pragma unroll
        for (int j = 0; j < 8; ++j)
            #pragma unroll
            for (int q = 0; q < 4; ++q) acc[i][j][q] = 0.0f;

    auto issue = [&](int buf, int k0) {
        uint32_t stg = sb + SM_STAGE + buf * STG;
        #pragma unroll
        for (int it = 0; it < 4; ++it) {          // A array
            int ch = tid + it * 256;
            int row = ch >> 3, c = ch & 7;
            uint32_t sw = sw128((uint32_t)(row << 7) + (c << 4));
            int tok = s_tok[row];
            uint32_t sz = (tok < 0) ? 0u : 16u;
            const __nv_bfloat16* src = (c < 4)
                ? g_xh + (size_t)(tok < 0 ? 0 : tok) * DIMD + k0 + c * 8
                : g_xl + (size_t)(tok < 0 ? 0 : tok) * DIMD + k0 + (c - 4) * 8;
            cpa16(stg + sw, src, sz);
        }
        #pragma unroll
        for (int it = 0; it < 4; ++it) {          // B array
            int ch = tid + it * 256;
            int row = ch >> 3, c = ch & 7;
            uint32_t sw = sw128((uint32_t)(row << 7) + (c << 4));
            size_t wb = ((size_t)e * HIDH + nt * 128 + row) * DIMD + k0;
            const __nv_bfloat16* src = (c < 4) ? g_w1h + wb + c * 8 : g_w1l + wb + (c - 4) * 8;
            cpa16(stg + STG_B + sw, src, 16u);
        }
        cp_commit();
    };

    const int KC = DIMD / 32;  // 16
    issue(0, 0);
    issue(1, 32);
    for (int kc = 0; kc < KC; ++kc) {
        if (kc + 2 < KC)      { issue((kc + 2) % 3, (kc + 2) * 32); cp_wait<2>(); }
        else if (kc + 1 < KC) { cp_wait<1>(); }
        else                  { cp_wait<0>(); }
        __syncthreads();
        tile_compute(sb + SM_STAGE + (kc % 3) * STG, wm, wn, lane, acc);
        __syncthreads();
    }

    // epilogue: +bias, exact GELU, split, store H (private expert region)
    int r_lo = lane >> 2, cb = (lane & 3) * 2;
    size_t slot0 = (size_t)e * ECAP + mt * 128;
    const float* b1e = b1 + (size_t)e * HIDH;
    #pragma unroll
    for (int mi = 0; mi < 2; ++mi)
        #pragma unroll
        for (int hh = 0; hh < 2; ++hh) {
            int row = wm * 32 + mi * 16 + hh * 8 + r_lo;
            if (row >= vrows) continue;
            size_t sbase = (slot0 + row) * HIDH;
            #pragma unroll
            for (int ni = 0; ni < 8; ++ni) {
                int col = nt * 128 + wn * 64 + ni * 8 + cb;
                float v0 = acc[mi][ni][hh * 2 + 0] + b1e[col];
                float v1 = acc[mi][ni][hh * 2 + 1] + b1e[col + 1];
                float q0 = 0.5f * v0 * (1.0f + erff(v0 * 0.70710678118654752f));
                float q1 = 0.5f * v1 * (1.0f + erff(v1 * 0.70710678118654752f));
                __nv_bfloat16 h0 = __float2bfloat16(q0), h1 = __float2bfloat16(q1);
                __nv_bfloat16 l0 = __float2bfloat16(q0 - __bfloat162float(h0));
                __nv_bfloat16 l1 = __float2bfloat16(q1 - __bfloat162float(h1));
                *(__nv_bfloat162*)(g_hh + sbase + col) = __halves2bfloat162(h0, h1);
                *(__nv_bfloat162*)(g_hl + sbase + col) = __halves2bfloat162(l0, l1);
            }
        }
}

// ---------------- GEMM2: Y = H @ W2 + b2; out[tok] += w * Y ----------------
__global__ __launch_bounds__(256, 2) void k_gemm2(const float* __restrict__ b2,
                                                  float* __restrict__ out) {
    int e = blockIdx.z, mt = blockIdx.y, nt = blockIdx.x;
    int cnt = g_cnt[e];
    if (cnt > ECAP) cnt = ECAP;
    if (mt * 128 >= cnt) return;

    uint32_t sb = smem_u32(smc);
    int tid = threadIdx.x, wid = tid >> 5, lane = tid & 31;
    int wm = wid & 3, wn = wid >> 2;
    int* s_tok = (int*)smc;
    float* s_wgt = (float*)(smc + 512);
    if (tid < 128) {
        int gi = mt * 128 + tid;
        bool ok = gi < cnt;
        s_tok[tid] = ok ? g_tok[e * ECAP + gi] : -1;
        s_wgt[tid] = ok ? g_wgt[e * ECAP + gi] : 0.0f;
    }
    __syncthreads();

    float acc[2][8][4];
    #pragma unroll
    for (int i = 0; i < 2; ++i)
        #pragma unroll
        for (int j = 0; j < 8; ++j)
            #pragma unroll
            for (int q = 0; q < 4; ++q) acc[i][j][q] = 0.0f;

    auto issue = [&](int buf, int k0) {
        uint32_t stg = sb + SM_STAGE + buf * STG;
        #pragma unroll
        for (int it = 0; it < 4; ++it) {          // A: hidden rows (pre-split)
            int ch = tid + it * 256;
            int row = ch >> 3, c = ch & 7;
            uint32_t sw = sw128((uint32_t)(row << 7) + (c << 4));
            size_t ab = ((size_t)e * ECAP + mt * 128 + row) * HIDH + k0;
            const __nv_bfloat16* src = (c < 4) ? g_hh + ab + c * 8 : g_hl + ab + (c - 4) * 8;
            cpa16(stg + sw, src, 16u);
        }
        #pragma unroll
        for (int it = 0; it < 4; ++it) {          // B: W2^T rows
            int ch = tid + it * 256;
            int row = ch >> 3, c = ch & 7;
            uint32_t sw = sw128((uint32_t)(row << 7) + (c << 4));
            size_t wb = ((size_t)e * DIMD + nt * 128 + row) * HIDH + k0;
            const __nv_bfloat16* src = (c < 4) ? g_w2h + wb + c * 8 : g_w2l + wb + (c - 4) * 8;
            cpa16(stg + STG_B + sw, src, 16u);
        }
        cp_commit();
    };

    const int KC = HIDH / 32;  // 32
    issue(0, 0);
    issue(1, 32);
    for (int kc = 0; kc < KC; ++kc) {
        if (kc + 2 < KC)      { issue((kc + 2) % 3, (kc + 2) * 32); cp_wait<2>(); }
        else if (kc + 1 < KC) { cp_wait<1>(); }
        else                  { cp_wait<0>(); }
        __syncthreads();
        tile_compute(sb + SM_STAGE + (kc % 3) * STG, wm, wn, lane, acc);
        __syncthreads();
    }

    // epilogue: +b2, weighted scatter-add into out
    int r_lo = lane >> 2, cb = (lane & 3) * 2;
    const float* b2e = b2 + (size_t)e * DIMD;
    #pragma unroll
    for (int mi = 0; mi < 2; ++mi)
        #pragma unroll
        for (int hh = 0; hh < 2; ++hh) {
            int row = wm * 32 + mi * 16 + hh * 8 + r_lo;
            int tok = s_tok[row];
            float w = s_wgt[row];
            if (tok < 0 || w == 0.0f) continue;
            float* orow = out + (size_t)tok * DIMD;
            #pragma unroll
            for (int ni = 0; ni < 8; ++ni) {
                int col = nt * 128 + wn * 64 + ni * 8 + cb;
                float y0 = acc[mi][ni][hh * 2 + 0] + b2e[col];
                float y1 = acc[mi][ni][hh * 2 + 1] + b2e[col + 1];
                atomicAdd(orow + col,     w * y0);
                atomicAdd(orow + col + 1, w * y1);
            }
        }
}

// ---------------- launch ----------------
extern "C" void kernel_launch(void* const* d_in, const int* in_sizes, int n_in,
                              void* d_out, int out_size) {
    const float* x  = (const float*)d_in[0];
    const float* rt = (const float*)d_in[1];
    const float* W1 = (const float*)d_in[2];
    const float* b1 = (const float*)d_in[3];
    const float* W2 = (const float*)d_in[4];
    const float* b2 = (const float*)d_in[5];
    float* out = (float*)d_out;

    cudaFuncSetAttribute(k_gemm1, cudaFuncAttributeMaxDynamicSharedMemorySize, SMEM_DYN);
    cudaFuncSetAttribute(k_gemm2, cudaFuncAttributeMaxDynamicSharedMemorySize, SMEM_DYN);

    dim3 tb(32, 8);
    // order chosen so k_gemm1 is the 4th launch (ncu -s window)
    k_split_x<<<(TOKS * DIMD / 4 + 255) / 256, 256>>>(x);       // also zeros g_cnt
    k_scatter<<<TOKS / 256, 256>>>(rt);
    k_tsplit<<<dim3(HIDH / 32, DIMD / 32, NEXP), tb>>>(W1, 0, DIMD, HIDH);
    k_gemm1<<<dim3(HIDH / 128, ECAP / 128, NEXP), 256, SMEM_DYN>>>(b1);
    k_tsplit<<<dim3(DIMD / 32, HIDH / 32, NEXP), tb>>>(W2, 1, HIDH, DIMD);
    k_init_out<<<256, 256>>>(out, out_size / 4);
    k_gemm2<<<dim3(DIMD / 128, ECAP / 128, NEXP), 256, SMEM_DYN>>>(b2, out);
}

// round 8
// speedup vs baseline: 1.4764x; 1.4242x over previous
#include <cuda_runtime.h>
#include <cuda_fp16.h>
#include <stdint.h>

#define TOKS 8192
#define DIMD 512
#define HIDH 1024
#define NEXP 16
#define ECAP 2048                    // fixed capacity per expert (mean 1024, >30 sigma)
#define HROWS (NEXP * ECAP)

// ---------------- device scratch ----------------
__device__ int   g_cnt[NEXP];
__device__ int   g_tok[NEXP * ECAP];
__device__ float g_wgt[NEXP * ECAP];
__device__ __align__(256) __half g_xh[TOKS * DIMD];                  // x hi (fp16)
__device__ __align__(256) __half g_w1h[NEXP * HIDH * DIMD];          // W1^T hi: [e][h][d]
__device__ __align__(256) __half g_w1l[NEXP * HIDH * DIMD];          // W1^T lo
__device__ __align__(256) __half g_w2h[NEXP * DIMD * HIDH];          // W2^T hi: [e][dout][h]
__device__ __align__(256) __half g_w2l[NEXP * DIMD * HIDH];          // W2^T lo
__device__ __align__(256) __half g_hh[(size_t)HROWS * HIDH];         // gelu hidden (fp16)

// ---------------- helpers ----------------
__device__ __forceinline__ uint32_t smem_u32(const void* p) {
    uint32_t a;
    asm("{ .reg .u64 t; cvta.to.shared.u64 t, %1; cvt.u32.u64 %0, t; }" : "=r"(a) : "l"(p));
    return a;
}
__device__ __forceinline__ uint32_t sw128(uint32_t o) { return o ^ ((o >> 3) & 0x70); }
__device__ __forceinline__ uint32_t sw64(uint32_t o)  { return o ^ ((o >> 3) & 0x30); }

__device__ __forceinline__ void cpa16(uint32_t dst, const void* src, uint32_t sz) {
    asm volatile("cp.async.cg.shared.global [%0], [%1], 16, %2;"
                 :: "r"(dst), "l"(src), "r"(sz) : "memory");
}
__device__ __forceinline__ void cp_commit() {
    asm volatile("cp.async.commit_group;" ::: "memory");
}
template <int N>
__device__ __forceinline__ void cp_wait() {
    asm volatile("cp.async.wait_group %0;" :: "n"(N) : "memory");
}
__device__ __forceinline__ void ldsm4(uint32_t* r, uint32_t addr) {
    asm volatile("ldmatrix.sync.aligned.m8n8.x4.shared.b16 {%0,%1,%2,%3}, [%4];"
                 : "=r"(r[0]), "=r"(r[1]), "=r"(r[2]), "=r"(r[3]) : "r"(addr));
}
__device__ __forceinline__ void mma_f16(float* d, const uint32_t* a, const uint32_t* b) {
    asm volatile(
        "mma.sync.aligned.m16n8k16.row.col.f32.f16.f16.f32 "
        "{%0,%1,%2,%3}, {%4,%5,%6,%7}, {%8,%9}, {%0,%1,%2,%3};"
        : "+f"(d[0]), "+f"(d[1]), "+f"(d[2]), "+f"(d[3])
        : "r"(a[0]), "r"(a[1]), "r"(a[2]), "r"(a[3]), "r"(b[0]), "r"(b[1]));
}

// smem: s_tok[128] @0, s_wgt[128] @512, 4 stages @1024
// stage: A hi [128 x 64B, SW64] @0 ; B [128 x 128B = hi K32 | lo K32, SW128] @8192
#define OFF_B    8192
#define STG      24576
#define SM_STAGE 1024
#define SMEM_DYN (SM_STAGE + 4 * STG)   // 99328

extern __shared__ __align__(1024) char smc[];

// ---------------- prep kernels ----------------
__global__ void k_split_x(const float* __restrict__ x) {
    if (blockIdx.x == 0 && threadIdx.x < NEXP) g_cnt[threadIdx.x] = 0;
    int i = blockIdx.x * 256 + threadIdx.x;
    if (i < TOKS * DIMD / 4) {
        float4 v = ((const float4*)x)[i];
        __half2 a = __floats2half2_rn(v.x, v.y);
        __half2 b = __floats2half2_rn(v.z, v.w);
        ((__half2*)g_xh)[i * 2]     = a;
        ((__half2*)g_xh)[i * 2 + 1] = b;
    }
}

// single-pass routing into fixed-capacity per-expert lists
__global__ void k_scatter(const float* __restrict__ rt) {
    __shared__ int s_cnt[NEXP], s_base[NEXP];
    int tid = threadIdx.x;
    int n = blockIdx.x * 256 + tid;
    if (tid < NEXP) s_cnt[tid] = 0;
    __syncthreads();
    float v[NEXP];
    const float4* r4 = (const float4*)(rt + (size_t)n * NEXP);
    float4 a = r4[0], b = r4[1], c = r4[2], d = r4[3];
    v[0]=a.x; v[1]=a.y; v[2]=a.z; v[3]=a.w; v[4]=b.x; v[5]=b.y; v[6]=b.z; v[7]=b.w;
    v[8]=c.x; v[9]=c.y; v[10]=c.z; v[11]=c.w; v[12]=d.x; v[13]=d.y; v[14]=d.z; v[15]=d.w;
    int le[4]; float lv[4]; int ls[4]; int k = 0;
    #pragma unroll
    for (int e = 0; e < NEXP; ++e)
        if (v[e] > 0.0f && k < 4) { le[k] = e; lv[k] = v[e]; ls[k] = atomicAdd(&s_cnt[e], 1); ++k; }
    __syncthreads();
    if (tid < NEXP) s_base[tid] = atomicAdd(&g_cnt[tid], s_cnt[tid]);
    __syncthreads();
    for (int j = 0; j < k; ++j) {
        int slot = s_base[le[j]] + ls[j];
        if (slot < ECAP) { g_tok[le[j] * ECAP + slot] = n; g_wgt[le[j] * ECAP + slot] = lv[j]; }
    }
}

// transpose + fp16 hi/lo split: W [e][R][C] (C contig) -> T [e][C][R]
__global__ void k_tsplit(const float* __restrict__ W, int which, int R, int C) {
    __shared__ float tile[32][33];
    int e = blockIdx.z, c0 = blockIdx.x * 32, r0 = blockIdx.y * 32;
    const float* We = W + (size_t)e * R * C;
    int tx = threadIdx.x, ty = threadIdx.y;
    for (int i = ty; i < 32; i += 8)
        tile[i][tx] = We[(size_t)(r0 + i) * C + c0 + tx];
    __syncthreads();
    __half* Th = (which ? g_w2h : g_w1h) + (size_t)e * R * C;
    __half* Tl = (which ? g_w2l : g_w1l) + (size_t)e * R * C;
    int tid = ty * 32 + tx;
    #pragma unroll
    for (int w = tid; w < 512; w += 256) {
        int c = w >> 4, rp = (w & 15) * 2;
        float v0 = tile[rp][c], v1 = tile[rp + 1][c];
        __half h0 = __float2half(v0), h1 = __float2half(v1);
        __half l0 = __float2half(v0 - __half2float(h0));
        __half l1 = __float2half(v1 - __half2float(h1));
        size_t o = (size_t)(c0 + c) * R + r0 + rp;
        *(__half2*)(Th + o) = __halves2half2(h0, h1);
        *(__half2*)(Tl + o) = __halves2half2(l0, l1);
    }
}

__global__ void k_init_out(float* out, int n4) {
    int stride = gridDim.x * blockDim.x;
    float4 z = make_float4(0.f, 0.f, 0.f, 0.f);
    for (int i = blockIdx.x * blockDim.x + threadIdx.x; i < n4; i += stride)
        ((float4*)out)[i] = z;
}

// ---------------- GEMM tile compute ----------------
// CTA 128x128, BK=32 per stage, 8 warps: wm = wid&3 (32 rows), wn = wid>>2 (64 cols)
// products: ah*bh + ah*bl (A lo dropped; fp16 precision budget)
__device__ __forceinline__ void tile_compute(uint32_t stg, int wm, int wn, int lane,
                                             float acc[2][8][4]) {
    int arow = lane & 15, acol = (lane >> 4) << 4;
    int brow = ((lane >> 4) << 3) + (lane & 7), bcol = ((lane >> 3) & 1) << 4;
    #pragma unroll
    for (int ks = 0; ks < 2; ++ks) {
        uint32_t ah[2][4], bh[4][4], bl[4][4];
        #pragma unroll
        for (int mi = 0; mi < 2; ++mi) {
            uint32_t rb = (uint32_t)((wm * 32 + mi * 16 + arow) << 6);
            ldsm4(ah[mi], stg + sw64(rb + ks * 32 + acol));
        }
        #pragma unroll
        for (int np = 0; np < 4; ++np) {
            uint32_t rb = (uint32_t)((wn * 64 + np * 16 + brow) << 7);
            ldsm4(bh[np], stg + OFF_B + sw128(rb + ks * 32 + bcol));
            ldsm4(bl[np], stg + OFF_B + sw128(rb + 64 + ks * 32 + bcol));
        }
        #pragma unroll
        for (int mi = 0; mi < 2; ++mi)
            #pragma unroll
            for (int np = 0; np < 4; ++np) {
                mma_f16(acc[mi][np * 2],     ah[mi], &bh[np][0]);
                mma_f16(acc[mi][np * 2],     ah[mi], &bl[np][0]);
                mma_f16(acc[mi][np * 2 + 1], ah[mi], &bh[np][2]);
                mma_f16(acc[mi][np * 2 + 1], ah[mi], &bl[np][2]);
            }
    }
}

// ---------------- GEMM1: H = gelu(Xg @ W1 + b1) -> fp16 ----------------
__global__ __launch_bounds__(256, 2) void k_gemm1(const float* __restrict__ b1) {
    int e = blockIdx.z, mt = blockIdx.y, nt = blockIdx.x;
    int cnt = g_cnt[e];
    if (cnt > ECAP) cnt = ECAP;
    if (mt * 128 >= cnt) return;
    int vrows = cnt - mt * 128;
    if (vrows > 128) vrows = 128;

    uint32_t sb = smem_u32(smc);
    int tid = threadIdx.x, wid = tid >> 5, lane = tid & 31;
    int wm = wid & 3, wn = wid >> 2;
    int* s_tok = (int*)smc;
    if (tid < 128) {
        int gi = mt * 128 + tid;
        s_tok[tid] = (gi < cnt) ? g_tok[e * ECAP + gi] : -1;
    }
    __syncthreads();

    float acc[2][8][4];
    #pragma unroll
    for (int i = 0; i < 2; ++i)
        #pragma unroll
        for (int j = 0; j < 8; ++j)
            #pragma unroll
            for (int q = 0; q < 4; ++q) acc[i][j][q] = 0.0f;

    auto issue = [&](int buf, int k0) {
        uint32_t stg = sb + SM_STAGE + buf * STG;
        #pragma unroll
        for (int it = 0; it < 2; ++it) {          // A hi: 512 chunks of 16B
            int ch = tid + it * 256;
            int row = ch >> 2, c = ch & 3;
            int tok = s_tok[row];
            uint32_t sz = (tok < 0) ? 0u : 16u;
            const __half* src = g_xh + (size_t)(tok < 0 ? 0 : tok) * DIMD + k0 + c * 8;
            cpa16(stg + sw64((uint32_t)(row << 6) + (c << 4)), src, sz);
        }
        #pragma unroll
        for (int it = 0; it < 4; ++it) {          // B hi|lo: 1024 chunks
            int ch = tid + it * 256;
            int row = ch >> 3, c = ch & 7;
            size_t wb = ((size_t)e * HIDH + nt * 128 + row) * DIMD + k0;
            const __half* src = (c < 4) ? g_w1h + wb + c * 8 : g_w1l + wb + (c - 4) * 8;
            cpa16(stg + OFF_B + sw128((uint32_t)(row << 7) + (c << 4)), src, 16u);
        }
        cp_commit();
    };

    const int KC = DIMD / 32;  // 16
    issue(0, 0);
    issue(1, 32);
    for (int kc = 0; kc < KC; ++kc) {
        if (kc + 2 < KC)      { issue((kc + 2) & 3, (kc + 2) * 32); cp_wait<2>(); }
        else if (kc + 1 < KC) { cp_wait<1>(); }
        else                  { cp_wait<0>(); }
        __syncthreads();
        tile_compute(sb + SM_STAGE + (kc & 3) * STG, wm, wn, lane, acc);
        // no trailing sync: writer stage (kc+3)&3 never collides with reader (kc)&3
    }

    // epilogue: +bias, exact GELU, store fp16 hidden (private expert region)
    int r_lo = lane >> 2, cb = (lane & 3) * 2;
    size_t slot0 = (size_t)e * ECAP + mt * 128;
    const float* b1e = b1 + (size_t)e * HIDH;
    #pragma unroll
    for (int mi = 0; mi < 2; ++mi)
        #pragma unroll
        for (int hh = 0; hh < 2; ++hh) {
            int row = wm * 32 + mi * 16 + hh * 8 + r_lo;
            if (row >= vrows) continue;
            size_t sbase = (slot0 + row) * HIDH;
            #pragma unroll
            for (int ni = 0; ni < 8; ++ni) {
                int col = nt * 128 + wn * 64 + ni * 8 + cb;
                float v0 = acc[mi][ni][hh * 2 + 0] + b1e[col];
                float v1 = acc[mi][ni][hh * 2 + 1] + b1e[col + 1];
                float q0 = 0.5f * v0 * (1.0f + erff(v0 * 0.70710678118654752f));
                float q1 = 0.5f * v1 * (1.0f + erff(v1 * 0.70710678118654752f));
                *(__half2*)(g_hh + sbase + col) = __floats2half2_rn(q0, q1);
            }
        }
}

// ---------------- GEMM2: Y = H @ W2 + b2; out[tok] += w * Y ----------------
__global__ __launch_bounds__(256, 2) void k_gemm2(const float* __restrict__ b2,
                                                  float* __restrict__ out) {
    int e = blockIdx.z, mt = blockIdx.y, nt = blockIdx.x;
    int cnt = g_cnt[e];
    if (cnt > ECAP) cnt = ECAP;
    if (mt * 128 >= cnt) return;

    uint32_t sb = smem_u32(smc);
    int tid = threadIdx.x, wid = tid >> 5, lane = tid & 31;
    int wm = wid & 3, wn = wid >> 2;
    int* s_tok = (int*)smc;
    float* s_wgt = (float*)(smc + 512);
    if (tid < 128) {
        int gi = mt * 128 + tid;
        bool ok = gi < cnt;
        s_tok[tid] = ok ? g_tok[e * ECAP + gi] : -1;
        s_wgt[tid] = ok ? g_wgt[e * ECAP + gi] : 0.0f;
    }
    __syncthreads();

    float acc[2][8][4];
    #pragma unroll
    for (int i = 0; i < 2; ++i)
        #pragma unroll
        for (int j = 0; j < 8; ++j)
            #pragma unroll
            for (int q = 0; q < 4; ++q) acc[i][j][q] = 0.0f;

    auto issue = [&](int buf, int k0) {
        uint32_t stg = sb + SM_STAGE + buf * STG;
        #pragma unroll
        for (int it = 0; it < 2; ++it) {          // A: hidden fp16 rows
            int ch = tid + it * 256;
            int row = ch >> 2, c = ch & 3;
            const __half* src = g_hh + ((size_t)e * ECAP + mt * 128 + row) * HIDH + k0 + c * 8;
            cpa16(stg + sw64((uint32_t)(row << 6) + (c << 4)), src, 16u);
        }
        #pragma unroll
        for (int it = 0; it < 4; ++it) {          // B: W2^T hi|lo
            int ch = tid + it * 256;
            int row = ch >> 3, c = ch & 7;
            size_t wb = ((size_t)e * DIMD + nt * 128 + row) * HIDH + k0;
            const __half* src = (c < 4) ? g_w2h + wb + c * 8 : g_w2l + wb + (c - 4) * 8;
            cpa16(stg + OFF_B + sw128((uint32_t)(row << 7) + (c << 4)), src, 16u);
        }
        cp_commit();
    };

    const int KC = HIDH / 32;  // 32
    issue(0, 0);
    issue(1, 32);
    for (int kc = 0; kc < KC; ++kc) {
        if (kc + 2 < KC)      { issue((kc + 2) & 3, (kc + 2) * 32); cp_wait<2>(); }
        else if (kc + 1 < KC) { cp_wait<1>(); }
        else                  { cp_wait<0>(); }
        __syncthreads();
        tile_compute(sb + SM_STAGE + (kc & 3) * STG, wm, wn, lane, acc);
    }

    // epilogue: +b2, weighted scatter-add into out
    int r_lo = lane >> 2, cb = (lane & 3) * 2;
    const float* b2e = b2 + (size_t)e * DIMD;
    #pragma unroll
    for (int mi = 0; mi < 2; ++mi)
        #pragma unroll
        for (int hh = 0; hh < 2; ++hh) {
            int row = wm * 32 + mi * 16 + hh * 8 + r_lo;
            int tok = s_tok[row];
            float w = s_wgt[row];
            if (tok < 0 || w == 0.0f) continue;
            float* orow = out + (size_t)tok * DIMD;
            #pragma unroll
            for (int ni = 0; ni < 8; ++ni) {
                int col = nt * 128 + wn * 64 + ni * 8 + cb;
                float y0 = acc[mi][ni][hh * 2 + 0] + b2e[col];
                float y1 = acc[mi][ni][hh * 2 + 1] + b2e[col + 1];
                atomicAdd(orow + col,     w * y0);
                atomicAdd(orow + col + 1, w * y1);
            }
        }
}

// ---------------- launch ----------------
extern "C" void kernel_launch(void* const* d_in, const int* in_sizes, int n_in,
                              void* d_out, int out_size) {
    const float* x  = (const float*)d_in[0];
    const float* rt = (const float*)d_in[1];
    const float* W1 = (const float*)d_in[2];
    const float* b1 = (const float*)d_in[3];
    const float* W2 = (const float*)d_in[4];
    const float* b2 = (const float*)d_in[5];
    float* out = (float*)d_out;

    cudaFuncSetAttribute(k_gemm1, cudaFuncAttributeMaxDynamicSharedMemorySize, SMEM_DYN);
    cudaFuncSetAttribute(k_gemm2, cudaFuncAttributeMaxDynamicSharedMemorySize, SMEM_DYN);

    dim3 tb(32, 8);
    // order chosen so k_gemm1 is the 4th launch (ncu -s window)
    k_split_x<<<(TOKS * DIMD / 4 + 255) / 256, 256>>>(x);       // also zeros g_cnt
    k_scatter<<<TOKS / 256, 256>>>(rt);
    k_tsplit<<<dim3(HIDH / 32, DIMD / 32, NEXP), tb>>>(W1, 0, DIMD, HIDH);
    k_gemm1<<<dim3(HIDH / 128, ECAP / 128, NEXP), 256, SMEM_DYN>>>(b1);
    k_tsplit<<<dim3(DIMD / 32, HIDH / 32, NEXP), tb>>>(W2, 1, HIDH, DIMD);
    k_init_out<<<256, 256>>>(out, out_size / 4);
    k_gemm2<<<dim3(DIMD / 128, ECAP / 128, NEXP), 256, SMEM_DYN>>>(b2, out);
}

// round 9
// speedup vs baseline: 2.0664x; 1.3997x over previous
#include <cuda_runtime.h>
#include <cuda_fp16.h>
#include <stdint.h>

#define TOKS 8192
#define DIMD 512
#define HIDH 1024
#define NEXP 16
#define ECAP 2048                    // fixed capacity per expert (mean 1024, >30 sigma)
#define HROWS (NEXP * ECAP)

// ---------------- device scratch ----------------
__device__ int   g_cnt[NEXP];
__device__ int   g_tok[NEXP * ECAP];
__device__ float g_wgt[NEXP * ECAP];
__device__ __align__(256) __half g_xh[TOKS * DIMD];                  // x (fp16)
__device__ __align__(256) __half g_w1h[NEXP * HIDH * DIMD];          // W1^T: [e][h][d] fp16
__device__ __align__(256) __half g_w2h[NEXP * DIMD * HIDH];          // W2^T: [e][dout][h] fp16
__device__ __align__(256) __half g_hh[(size_t)HROWS * HIDH];         // gelu hidden (fp16)

// ---------------- helpers ----------------
__device__ __forceinline__ uint32_t smem_u32(const void* p) {
    uint32_t a;
    asm("{ .reg .u64 t; cvta.to.shared.u64 t, %1; cvt.u32.u64 %0, t; }" : "=r"(a) : "l"(p));
    return a;
}
__device__ __forceinline__ uint32_t sw64(uint32_t o) { return o ^ ((o >> 3) & 0x30); }

__device__ __forceinline__ void cpa16(uint32_t dst, const void* src, uint32_t sz) {
    asm volatile("cp.async.cg.shared.global [%0], [%1], 16, %2;"
                 :: "r"(dst), "l"(src), "r"(sz) : "memory");
}
__device__ __forceinline__ void cp_commit() {
    asm volatile("cp.async.commit_group;" ::: "memory");
}
template <int N>
__device__ __forceinline__ void cp_wait() {
    asm volatile("cp.async.wait_group %0;" :: "n"(N) : "memory");
}
__device__ __forceinline__ void ldsm4(uint32_t* r, uint32_t addr) {
    asm volatile("ldmatrix.sync.aligned.m8n8.x4.shared.b16 {%0,%1,%2,%3}, [%4];"
                 : "=r"(r[0]), "=r"(r[1]), "=r"(r[2]), "=r"(r[3]) : "r"(addr));
}
__device__ __forceinline__ void mma_f16(float* d, const uint32_t* a, const uint32_t* b) {
    asm volatile(
        "mma.sync.aligned.m16n8k16.row.col.f32.f16.f16.f32 "
        "{%0,%1,%2,%3}, {%4,%5,%6,%7}, {%8,%9}, {%0,%1,%2,%3};"
        : "+f"(d[0]), "+f"(d[1]), "+f"(d[2]), "+f"(d[3])
        : "r"(a[0]), "r"(a[1]), "r"(a[2]), "r"(a[3]), "r"(b[0]), "r"(b[1]));
}

// smem: s_tok[128] @0, s_wgt[128] @512, 6 stages @1024
// stage (BK=32): A [128 x 64B, SW64] @0 ; B [128 x 64B, SW64] @8192
#define OFF_B    8192
#define STG      16384
#define SM_STAGE 1024
#define SMEM_DYN (SM_STAGE + 6 * STG)   // 99328

extern __shared__ __align__(1024) char smc[];

// ---------------- prep kernels ----------------
__global__ void k_split_x(const float* __restrict__ x) {
    if (blockIdx.x == 0 && threadIdx.x < NEXP) g_cnt[threadIdx.x] = 0;
    int i = blockIdx.x * 256 + threadIdx.x;
    if (i < TOKS * DIMD / 4) {
        float4 v = ((const float4*)x)[i];
        ((__half2*)g_xh)[i * 2]     = __floats2half2_rn(v.x, v.y);
        ((__half2*)g_xh)[i * 2 + 1] = __floats2half2_rn(v.z, v.w);
    }
}

// single-pass routing into fixed-capacity per-expert lists
__global__ void k_scatter(const float* __restrict__ rt) {
    __shared__ int s_cnt[NEXP], s_base[NEXP];
    int tid = threadIdx.x;
    int n = blockIdx.x * 256 + tid;
    if (tid < NEXP) s_cnt[tid] = 0;
    __syncthreads();
    float v[NEXP];
    const float4* r4 = (const float4*)(rt + (size_t)n * NEXP);
    float4 a = r4[0], b = r4[1], c = r4[2], d = r4[3];
    v[0]=a.x; v[1]=a.y; v[2]=a.z; v[3]=a.w; v[4]=b.x; v[5]=b.y; v[6]=b.z; v[7]=b.w;
    v[8]=c.x; v[9]=c.y; v[10]=c.z; v[11]=c.w; v[12]=d.x; v[13]=d.y; v[14]=d.z; v[15]=d.w;
    int le[4]; float lv[4]; int ls[4]; int k = 0;
    #pragma unroll
    for (int e = 0; e < NEXP; ++e)
        if (v[e] > 0.0f && k < 4) { le[k] = e; lv[k] = v[e]; ls[k] = atomicAdd(&s_cnt[e], 1); ++k; }
    __syncthreads();
    if (tid < NEXP) s_base[tid] = atomicAdd(&g_cnt[tid], s_cnt[tid]);
    __syncthreads();
    for (int j = 0; j < k; ++j) {
        int slot = s_base[le[j]] + ls[j];
        if (slot < ECAP) { g_tok[le[j] * ECAP + slot] = n; g_wgt[le[j] * ECAP + slot] = lv[j]; }
    }
}

// transpose + fp16 convert: W [e][R][C] (C contig) -> T [e][C][R]
__global__ void k_tsplit(const float* __restrict__ W, int which, int R, int C) {
    __shared__ float tile[32][33];
    int e = blockIdx.z, c0 = blockIdx.x * 32, r0 = blockIdx.y * 32;
    const float* We = W + (size_t)e * R * C;
    int tx = threadIdx.x, ty = threadIdx.y;
    for (int i = ty; i < 32; i += 8)
        tile[i][tx] = We[(size_t)(r0 + i) * C + c0 + tx];
    __syncthreads();
    __half* Th = (which ? g_w2h : g_w1h) + (size_t)e * R * C;
    int tid = ty * 32 + tx;
    #pragma unroll
    for (int w = tid; w < 512; w += 256) {
        int c = w >> 4, rp = (w & 15) * 2;
        size_t o = (size_t)(c0 + c) * R + r0 + rp;
        *(__half2*)(Th + o) = __floats2half2_rn(tile[rp][c], tile[rp + 1][c]);
    }
}

__global__ void k_init_out(float* out, int n4) {
    int stride = gridDim.x * blockDim.x;
    float4 z = make_float4(0.f, 0.f, 0.f, 0.f);
    for (int i = blockIdx.x * blockDim.x + threadIdx.x; i < n4; i += stride)
        ((float4*)out)[i] = z;
}

// ---------------- GEMM tile compute ----------------
// CTA 128x128, BK=32 per stage, 8 warps: wm = wid&3 (32 rows), wn = wid>>2 (64 cols)
__device__ __forceinline__ void tile_compute(uint32_t stg, int wm, int wn, int lane,
                                             float acc[2][8][4]) {
    int arow = lane & 15, acol = (lane >> 4) << 4;
    int brow = ((lane >> 4) << 3) + (lane & 7), bcol = ((lane >> 3) & 1) << 4;
    #pragma unroll
    for (int ks = 0; ks < 2; ++ks) {
        uint32_t ah[2][4], bh[4][4];
        #pragma unroll
        for (int mi = 0; mi < 2; ++mi) {
            uint32_t rb = (uint32_t)((wm * 32 + mi * 16 + arow) << 6);
            ldsm4(ah[mi], stg + sw64(rb + ks * 32 + acol));
        }
        #pragma unroll
        for (int np = 0; np < 4; ++np) {
            uint32_t rb = (uint32_t)((wn * 64 + np * 16 + brow) << 6);
            ldsm4(bh[np], stg + OFF_B + sw64(rb + ks * 32 + bcol));
        }
        #pragma unroll
        for (int mi = 0; mi < 2; ++mi)
            #pragma unroll
            for (int np = 0; np < 4; ++np) {
                mma_f16(acc[mi][np * 2],     ah[mi], &bh[np][0]);
                mma_f16(acc[mi][np * 2 + 1], ah[mi], &bh[np][2]);
            }
    }
}

// ---------------- GEMM1: H = gelu(Xg @ W1 + b1) -> fp16 ----------------
__global__ __launch_bounds__(256, 2) void k_gemm1(const float* __restrict__ b1) {
    int e = blockIdx.z, mt = blockIdx.y, nt = blockIdx.x;
    int cnt = g_cnt[e];
    if (cnt > ECAP) cnt = ECAP;
    if (mt * 128 >= cnt) return;
    int vrows = cnt - mt * 128;
    if (vrows > 128) vrows = 128;

    uint32_t sb = smem_u32(smc);
    int tid = threadIdx.x, wid = tid >> 5, lane = tid & 31;
    int wm = wid & 3, wn = wid >> 2;
    int* s_tok = (int*)smc;
    if (tid < 128) {
        int gi = mt * 128 + tid;
        s_tok[tid] = (gi < cnt) ? g_tok[e * ECAP + gi] : -1;
    }
    __syncthreads();

    float acc[2][8][4];
    #pragma unroll
    for (int i = 0; i < 2; ++i)
        #pragma unroll
        for (int j = 0; j < 8; ++j)
            #pragma unroll
            for (int q = 0; q < 4; ++q) acc[i][j][q] = 0.0f;

    auto issue = [&](int buf, int k0) {
        uint32_t stg = sb + SM_STAGE + buf * STG;
        #pragma unroll
        for (int it = 0; it < 2; ++it) {          // A: 512 chunks of 16B (gather)
            int ch = tid + it * 256;
            int row = ch >> 2, c = ch & 3;
            int tok = s_tok[row];
            uint32_t sz = (tok < 0) ? 0u : 16u;
            const __half* src = g_xh + (size_t)(tok < 0 ? 0 : tok) * DIMD + k0 + c * 8;
            cpa16(stg + sw64((uint32_t)(row << 6) + (c << 4)), src, sz);
        }
        #pragma unroll
        for (int it = 0; it < 2; ++it) {          // B: 512 chunks of 16B
            int ch = tid + it * 256;
            int row = ch >> 2, c = ch & 3;
            const __half* src = g_w1h + ((size_t)e * HIDH + nt * 128 + row) * DIMD + k0 + c * 8;
            cpa16(stg + OFF_B + sw64((uint32_t)(row << 6) + (c << 4)), src, 16u);
        }
        cp_commit();
    };

    const int KC = DIMD / 32;  // 16
    issue(0, 0); issue(1, 32); issue(2, 64); issue(3, 96);
    for (int kc = 0; kc < KC; ++kc) {
        if (kc + 4 < KC)       { issue((kc + 4) % 6, (kc + 4) * 32); cp_wait<4>(); }
        else if (kc + 4 == KC) { cp_wait<3>(); }
        else if (kc + 3 == KC) { cp_wait<2>(); }
        else if (kc + 2 == KC) { cp_wait<1>(); }
        else                   { cp_wait<0>(); }
        __syncthreads();
        tile_compute(sb + SM_STAGE + (kc % 6) * STG, wm, wn, lane, acc);
        // no trailing sync: writer stage (kc+4)%6 never collides with laggard reader (kc-1)%6
    }

    // epilogue: +bias, exact GELU, store fp16 hidden (private expert region)
    int r_lo = lane >> 2, cb = (lane & 3) * 2;
    size_t slot0 = (size_t)e * ECAP + mt * 128;
    const float* b1e = b1 + (size_t)e * HIDH;
    #pragma unroll
    for (int mi = 0; mi < 2; ++mi)
        #pragma unroll
        for (int hh = 0; hh < 2; ++hh) {
            int row = wm * 32 + mi * 16 + hh * 8 + r_lo;
            if (row >= vrows) continue;
            size_t sbase = (slot0 + row) * HIDH;
            #pragma unroll
            for (int ni = 0; ni < 8; ++ni) {
                int col = nt * 128 + wn * 64 + ni * 8 + cb;
                float v0 = acc[mi][ni][hh * 2 + 0] + b1e[col];
                float v1 = acc[mi][ni][hh * 2 + 1] + b1e[col + 1];
                float q0 = 0.5f * v0 * (1.0f + erff(v0 * 0.70710678118654752f));
                float q1 = 0.5f * v1 * (1.0f + erff(v1 * 0.70710678118654752f));
                *(__half2*)(g_hh + sbase + col) = __floats2half2_rn(q0, q1);
            }
        }
}

// ---------------- GEMM2: Y = H @ W2 + b2; out[tok] += w * Y ----------------
__global__ __launch_bounds__(256, 2) void k_gemm2(const float* __restrict__ b2,
                                                  float* __restrict__ out) {
    int e = blockIdx.z, mt = blockIdx.y, nt = blockIdx.x;
    int cnt = g_cnt[e];
    if (cnt > ECAP) cnt = ECAP;
    if (mt * 128 >= cnt) return;

    uint32_t sb = smem_u32(smc);
    int tid = threadIdx.x, wid = tid >> 5, lane = tid & 31;
    int wm = wid & 3, wn = wid >> 2;
    int* s_tok = (int*)smc;
    float* s_wgt = (float*)(smc + 512);
    if (tid < 128) {
        int gi = mt * 128 + tid;
        bool ok = gi < cnt;
        s_tok[tid] = ok ? g_tok[e * ECAP + gi] : -1;
        s_wgt[tid] = ok ? g_wgt[e * ECAP + gi] : 0.0f;
    }
    __syncthreads();

    float acc[2][8][4];
    #pragma unroll
    for (int i = 0; i < 2; ++i)
        #pragma unroll
        for (int j = 0; j < 8; ++j)
            #pragma unroll
            for (int q = 0; q < 4; ++q) acc[i][j][q] = 0.0f;

    auto issue = [&](int buf, int k0) {
        uint32_t stg = sb + SM_STAGE + buf * STG;
        #pragma unroll
        for (int it = 0; it < 2; ++it) {          // A: hidden fp16 rows
            int ch = tid + it * 256;
            int row = ch >> 2, c = ch & 3;
            const __half* src = g_hh + ((size_t)e * ECAP + mt * 128 + row) * HIDH + k0 + c * 8;
            cpa16(stg + sw64((uint32_t)(row << 6) + (c << 4)), src, 16u);
        }
        #pragma unroll
        for (int it = 0; it < 2; ++it) {          // B: W2^T rows
            int ch = tid + it * 256;
            int row = ch >> 2, c = ch & 3;
            const __half* src = g_w2h + ((size_t)e * DIMD + nt * 128 + row) * HIDH + k0 + c * 8;
            cpa16(stg + OFF_B + sw64((uint32_t)(row << 6) + (c << 4)), src, 16u);
        }
        cp_commit();
    };

    const int KC = HIDH / 32;  // 32
    issue(0, 0); issue(1, 32); issue(2, 64); issue(3, 96);
    for (int kc = 0; kc < KC; ++kc) {
        if (kc + 4 < KC)       { issue((kc + 4) % 6, (kc + 4) * 32); cp_wait<4>(); }
        else if (kc + 4 == KC) { cp_wait<3>(); }
        else if (kc + 3 == KC) { cp_wait<2>(); }
        else if (kc + 2 == KC) { cp_wait<1>(); }
        else                   { cp_wait<0>(); }
        __syncthreads();
        tile_compute(sb + SM_STAGE + (kc % 6) * STG, wm, wn, lane, acc);
    }

    // epilogue: +b2, weighted scatter-add into out
    int r_lo = lane >> 2, cb = (lane & 3) * 2;
    const float* b2e = b2 + (size_t)e * DIMD;
    #pragma unroll
    for (int mi = 0; mi < 2; ++mi)
        #pragma unroll
        for (int hh = 0; hh < 2; ++hh) {
            int row = wm * 32 + mi * 16 + hh * 8 + r_lo;
            int tok = s_tok[row];
            float w = s_wgt[row];
            if (tok < 0 || w == 0.0f) continue;
            float* orow = out + (size_t)tok * DIMD;
            #pragma unroll
            for (int ni = 0; ni < 8; ++ni) {
                int col = nt * 128 + wn * 64 + ni * 8 + cb;
                float y0 = acc[mi][ni][hh * 2 + 0] + b2e[col];
                float y1 = acc[mi][ni][hh * 2 + 1] + b2e[col + 1];
                atomicAdd(orow + col,     w * y0);
                atomicAdd(orow + col + 1, w * y1);
            }
        }
}

// ---------------- launch ----------------
extern "C" void kernel_launch(void* const* d_in, const int* in_sizes, int n_in,
                              void* d_out, int out_size) {
    const float* x  = (const float*)d_in[0];
    const float* rt = (const float*)d_in[1];
    const float* W1 = (const float*)d_in[2];
    const float* b1 = (const float*)d_in[3];
    const float* W2 = (const float*)d_in[4];
    const float* b2 = (const float*)d_in[5];
    float* out = (float*)d_out;

    cudaFuncSetAttribute(k_gemm1, cudaFuncAttributeMaxDynamicSharedMemorySize, SMEM_DYN);
    cudaFuncSetAttribute(k_gemm2, cudaFuncAttributeMaxDynamicSharedMemorySize, SMEM_DYN);

    dim3 tb(32, 8);
    // order chosen so k_gemm1 is the 4th launch (ncu -s window)
    k_split_x<<<(TOKS * DIMD / 4 + 255) / 256, 256>>>(x);       // also zeros g_cnt
    k_scatter<<<TOKS / 256, 256>>>(rt);
    k_tsplit<<<dim3(HIDH / 32, DIMD / 32, NEXP), tb>>>(W1, 0, DIMD, HIDH);
    k_gemm1<<<dim3(HIDH / 128, ECAP / 128, NEXP), 256, SMEM_DYN>>>(b1);
    k_tsplit<<<dim3(DIMD / 32, HIDH / 32, NEXP), tb>>>(W2, 1, HIDH, DIMD);
    k_init_out<<<256, 256>>>(out, out_size / 4);
    k_gemm2<<<dim3(DIMD / 128, ECAP / 128, NEXP), 256, SMEM_DYN>>>(b2, out);
}